// round 3
// baseline (speedup 1.0000x reference)
#include <cuda_runtime.h>
#include <cstdint>

#define NTHREADS 256
#define NEXP 8
#define DIN  64
#define HID  128
#define DOUT 64
#define ET   64
#define GRIDX 18
#define LN_EPS 1e-5f

// ---- shared memory float offsets ----
enum {
  OWS1 = 0,             // [64][128]   W1^T  (k-major)
  OWS2 = 8192,          // [128][128]  W2^T
  OWS3 = 24576,         // [128][64]   W3^T
  OB1  = 32768,         // 128
  OG1  = 32896,
  OBT1 = 33024,
  OB2  = 33152,
  OG2  = 33280,
  OBT2 = 33408,
  OB3  = 33536,         // 64
  OH1  = 33600,         // [128][66]  h1 (k-major, padded)
  OH2  = 42048,         // [128][66]  h2
  OXO  = 50496,         // x tile [64][65]  /  o tile [64][68] (union)
  ORED = 54848,         // 256
  ORED2= 55104,         // 256
  OMU  = 55360,         // 64
  ORS  = 55424,         // 64
  SMEMF= 55488          // total floats -> 221952 bytes
};

// ---- packed f32x2 helpers (Blackwell dual-rate fp32) ----
__device__ __forceinline__ unsigned long long pk2(float lo, float hi) {
  unsigned long long r;
  asm("mov.b64 %0, {%1,%2};" : "=l"(r) : "f"(lo), "f"(hi));
  return r;
}
__device__ __forceinline__ void upk2(unsigned long long v, float& lo, float& hi) {
  asm("mov.b64 {%0,%1}, %2;" : "=f"(lo), "=f"(hi) : "l"(v));
}
__device__ __forceinline__ void fma2(unsigned long long& d,
                                     unsigned long long a,
                                     unsigned long long b) {
  asm("fma.rn.f32x2 %0, %1, %2, %0;" : "+l"(d) : "l"(a), "l"(b));
}

// LayerNorm(+affine)+SiLU over 128-dim columns of h stored [k][e] stride 66.
__device__ __forceinline__ void ln_silu(float* sm, int oh, int og, int obt, int tid) {
  const int e = tid & 63;
  const int q = tid >> 6;         // 0..3, each covers 32 rows
  float s = 0.f, ss = 0.f;
  #pragma unroll 8
  for (int j = q * 32; j < q * 32 + 32; j++) {
    float v = sm[oh + j * 66 + e];
    s += v; ss += v * v;
  }
  sm[ORED + tid]  = s;
  sm[ORED2 + tid] = ss;
  __syncthreads();
  if (tid < 64) {
    float st  = sm[ORED + e] + sm[ORED + 64 + e] + sm[ORED + 128 + e] + sm[ORED + 192 + e];
    float sst = sm[ORED2 + e] + sm[ORED2 + 64 + e] + sm[ORED2 + 128 + e] + sm[ORED2 + 192 + e];
    float mu  = st * (1.f / 128.f);
    float var = sst * (1.f / 128.f) - mu * mu;
    var = fmaxf(var, 0.f);
    sm[OMU + e] = mu;
    sm[ORS + e] = rsqrtf(var + LN_EPS);
  }
  __syncthreads();
  const float mu = sm[OMU + e];
  const float rs = sm[ORS + e];
  #pragma unroll 8
  for (int j = q * 32; j < q * 32 + 32; j++) {
    float v = sm[oh + j * 66 + e];
    float y = (v - mu) * rs * sm[og + j] + sm[obt + j];
    float sg = 1.f / (1.f + __expf(-y));
    sm[oh + j * 66 + e] = y * sg;
  }
  __syncthreads();
}

__global__ void __launch_bounds__(NTHREADS, 1)
urmlp_kernel(const float* __restrict__ x,
             const float* __restrict__ W1, const float* __restrict__ b1,
             const float* __restrict__ g1, const float* __restrict__ bt1,
             const float* __restrict__ W2, const float* __restrict__ b2,
             const float* __restrict__ g2, const float* __restrict__ bt2,
             const float* __restrict__ W3, const float* __restrict__ b3,
             float* __restrict__ out, int E) {
  extern __shared__ float sm[];
  const int tid = threadIdx.x;
  const int n   = blockIdx.y;

  // ---- load expert weights to SMEM, transposed to [k][j] ----
  for (int i = tid; i < HID * DIN; i += NTHREADS) {      // W1_cat slice [128][64]
    int j = i >> 6, k = i & 63;
    sm[OWS1 + k * HID + j] = W1[n * HID * DIN + i];
  }
  for (int i = tid; i < HID * HID; i += NTHREADS) {      // W2[n] [128][128]
    int j = i >> 7, k = i & 127;
    sm[OWS2 + k * HID + j] = W2[n * HID * HID + i];
  }
  for (int i = tid; i < DOUT * HID; i += NTHREADS) {     // W3[n] [64][128]
    int j = i >> 7, k = i & 127;
    sm[OWS3 + k * DOUT + j] = W3[n * DOUT * HID + i];
  }
  if (tid < HID) {
    sm[OB1 + tid]  = b1[n * HID + tid];
    sm[OG1 + tid]  = g1[n * HID + tid];
    sm[OBT1 + tid] = bt1[n * HID + tid];
    sm[OB2 + tid]  = b2[n * HID + tid];
    sm[OG2 + tid]  = g2[n * HID + tid];
    sm[OBT2 + tid] = bt2[n * HID + tid];
    if (tid < DOUT) sm[OB3 + tid] = b3[n * DOUT + tid];
  }
  __syncthreads();

  // thread->tile mapping: warp = 4 edge-groups x 8 j-groups
  const int lane  = tid & 31;
  const int w     = tid >> 5;
  const int egl   = lane >> 3;              // 0..3
  const int jgl   = lane & 7;               // 0..7
  const int eg    = (w & 1) * 4 + egl;      // 0..7  -> edges eg*8..eg*8+7
  const int jg    = (w >> 1) * 8 + jgl;     // 0..31
  const int ebase = eg * 8;

  const int NT = (E + ET - 1) / ET;
  for (int t = blockIdx.x; t < NT; t += gridDim.x) {
    const int e0 = t * ET;

    // ---- load x tile [64 edges][64 feat], pad stride 65, zero-fill tail ----
    for (int i = tid; i < ET * DIN; i += NTHREADS) {
      int e = i >> 6, k = i & 63;
      float v = (e0 + e < E) ? x[(size_t)(e0 + e) * DIN + k] : 0.f;
      sm[OXO + e * 65 + k] = v;
    }
    __syncthreads();

    // ---- GEMM1: h1[j][e] = b1[j] + sum_k W1t[k][j] * x[e][k]  (pack over j) ----
    {
      unsigned long long acc[8][2];
      const unsigned long long bp0 = pk2(sm[OB1 + jg * 4 + 0], sm[OB1 + jg * 4 + 1]);
      const unsigned long long bp1 = pk2(sm[OB1 + jg * 4 + 2], sm[OB1 + jg * 4 + 3]);
      #pragma unroll
      for (int i = 0; i < 8; i++) { acc[i][0] = bp0; acc[i][1] = bp1; }
      #pragma unroll 4
      for (int k = 0; k < DIN; k++) {
        ulonglong2 wv = *(const ulonglong2*)&sm[OWS1 + k * HID + jg * 4];
        #pragma unroll
        for (int i = 0; i < 8; i++) {
          float xv = sm[OXO + (ebase + i) * 65 + k];
          unsigned long long xx = pk2(xv, xv);
          fma2(acc[i][0], xx, wv.x);
          fma2(acc[i][1], xx, wv.y);
        }
      }
      #pragma unroll
      for (int i = 0; i < 8; i++) {
        float v0, v1, v2, v3;
        upk2(acc[i][0], v0, v1);
        upk2(acc[i][1], v2, v3);
        int e = ebase + i;
        sm[OH1 + (jg * 4 + 0) * 66 + e] = v0;
        sm[OH1 + (jg * 4 + 1) * 66 + e] = v1;
        sm[OH1 + (jg * 4 + 2) * 66 + e] = v2;
        sm[OH1 + (jg * 4 + 3) * 66 + e] = v3;
      }
    }
    __syncthreads();

    ln_silu(sm, OH1, OG1, OBT1, tid);

    // ---- GEMM2: h2[j][e] = b2[j] + sum_k W2t[k][j] * h1[k][e]  (pack over e) ----
    {
      unsigned long long acc[4][4];
      #pragma unroll
      for (int c = 0; c < 4; c++) {
        float b = sm[OB2 + jg * 4 + c];
        unsigned long long bp = pk2(b, b);
        #pragma unroll
        for (int p = 0; p < 4; p++) acc[p][c] = bp;
      }
      #pragma unroll 2
      for (int k = 0; k < HID; k++) {
        unsigned long long hp[4];
        #pragma unroll
        for (int p = 0; p < 4; p++)
          hp[p] = *(const unsigned long long*)&sm[OH1 + k * 66 + ebase + 2 * p];
        float4 wv = *(const float4*)&sm[OWS2 + k * HID + jg * 4];
        unsigned long long wp0 = pk2(wv.x, wv.x), wp1 = pk2(wv.y, wv.y);
        unsigned long long wp2 = pk2(wv.z, wv.z), wp3 = pk2(wv.w, wv.w);
        #pragma unroll
        for (int p = 0; p < 4; p++) {
          fma2(acc[p][0], hp[p], wp0);
          fma2(acc[p][1], hp[p], wp1);
          fma2(acc[p][2], hp[p], wp2);
          fma2(acc[p][3], hp[p], wp3);
        }
      }
      #pragma unroll
      for (int c = 0; c < 4; c++) {
        int j = jg * 4 + c;
        #pragma unroll
        for (int p = 0; p < 4; p++)
          *(unsigned long long*)&sm[OH2 + j * 66 + ebase + 2 * p] = acc[p][c];
      }
    }
    __syncthreads();

    ln_silu(sm, OH2, OG2, OBT2, tid);

    // ---- GEMM3: o[e][j] = b3[j] + sum_k W3t[k][j] * h2[k][e]  (pack over e) ----
    {
      unsigned long long acc[4][2];
      #pragma unroll
      for (int c = 0; c < 2; c++) {
        float b = sm[OB3 + jg * 2 + c];
        unsigned long long bp = pk2(b, b);
        #pragma unroll
        for (int p = 0; p < 4; p++) acc[p][c] = bp;
      }
      #pragma unroll 2
      for (int k = 0; k < HID; k++) {
        unsigned long long hp[4];
        #pragma unroll
        for (int p = 0; p < 4; p++)
          hp[p] = *(const unsigned long long*)&sm[OH2 + k * 66 + ebase + 2 * p];
        float2 wv = *(const float2*)&sm[OWS3 + k * DOUT + jg * 2];
        unsigned long long wp0 = pk2(wv.x, wv.x), wp1 = pk2(wv.y, wv.y);
        #pragma unroll
        for (int p = 0; p < 4; p++) {
          fma2(acc[p][0], hp[p], wp0);
          fma2(acc[p][1], hp[p], wp1);
        }
      }
      // stage output as [e][j], stride 68 (16B-aligned rows)
      #pragma unroll
      for (int c = 0; c < 2; c++) {
        int j = jg * 2 + c;
        #pragma unroll
        for (int p = 0; p < 4; p++) {
          float lo, hi;
          upk2(acc[p][c], lo, hi);
          sm[OXO + (ebase + 2 * p + 0) * 68 + j] = lo;
          sm[OXO + (ebase + 2 * p + 1) * 68 + j] = hi;
        }
      }
    }
    __syncthreads();

    // ---- coalesced global store: out[n][e][j] ----
    {
      const size_t obase = (size_t)n * E * DOUT + (size_t)e0 * DOUT;
      #pragma unroll
      for (int r = 0; r < 4; r++) {
        int v = tid + r * NTHREADS;     // 0..1023 float4 slots
        int e = v >> 4, jq = v & 15;
        if (e0 + e < E) {
          float4 val = *(const float4*)&sm[OXO + e * 68 + jq * 4];
          *(float4*)&out[obase + (size_t)e * DOUT + jq * 4] = val;
        }
      }
    }
    __syncthreads();   // protect OXO before next tile's x load
  }
}

extern "C" void kernel_launch(void* const* d_in, const int* in_sizes, int n_in,
                              void* d_out, int out_size) {
  const float* x   = (const float*)d_in[0];
  const float* W1  = (const float*)d_in[1];
  const float* b1  = (const float*)d_in[2];
  const float* g1  = (const float*)d_in[3];
  const float* bt1 = (const float*)d_in[4];
  const float* W2  = (const float*)d_in[5];
  const float* b2  = (const float*)d_in[6];
  const float* g2  = (const float*)d_in[7];
  const float* bt2 = (const float*)d_in[8];
  const float* W3  = (const float*)d_in[9];
  const float* b3  = (const float*)d_in[10];
  float* out = (float*)d_out;
  const int E = in_sizes[0] / DIN;

  cudaFuncSetAttribute(urmlp_kernel, cudaFuncAttributeMaxDynamicSharedMemorySize,
                       SMEMF * sizeof(float));
  dim3 grid(GRIDX, NEXP);
  urmlp_kernel<<<grid, NTHREADS, SMEMF * sizeof(float)>>>(
      x, W1, b1, g1, bt1, W2, b2, g2, bt2, W3, b3, out, E);
}

// round 5
// speedup vs baseline: 1.1148x; 1.1148x over previous
#include <cuda_runtime.h>
#include <cstdint>

#define NTHREADS 512
#define NEXP 8
#define DIN  64
#define HID  128
#define DOUT 64
#define ET   64
#define GRIDX 18
#define LN_EPS 1e-5f

// ---- shared memory float offsets ----
enum {
  OWS1 = 0,             // [64][128]   W1^T  (k-major)
  OWS2 = 8192,          // [128][128]  W2^T
  OWS3 = 24576,         // [128][64]   W3^T
  OB1  = 32768,         // 128
  OG1  = 32896,
  OBT1 = 33024,
  OB2  = 33152,
  OG2  = 33280,
  OBT2 = 33408,
  OB3  = 33536,         // 64
  OH1  = 33600,         // [128][66]  h1 (j-major rows, e columns)
  OH2  = 42048,         // [128][66]  h2
  OXO  = 50496,         // x tile [64k][66e] transposed  /  o tile [64e][68j]
  ORED = 54848,         // 512
  ORED2= 55360,         // 512
  OMU  = 55872,         // 64
  ORS  = 55936,         // 64
  SMEMF= 56000          // 224000 bytes
};

// ---- packed f32x2 helpers ----
__device__ __forceinline__ unsigned long long pk2(float lo, float hi) {
  unsigned long long r;
  asm("mov.b64 %0, {%1,%2};" : "=l"(r) : "f"(lo), "f"(hi));
  return r;
}
__device__ __forceinline__ void upk2(unsigned long long v, float& lo, float& hi) {
  asm("mov.b64 {%0,%1}, %2;" : "=f"(lo), "=f"(hi) : "l"(v));
}
__device__ __forceinline__ void fma2(unsigned long long& d,
                                     unsigned long long a,
                                     unsigned long long b) {
  asm("fma.rn.f32x2 %0, %1, %2, %0;" : "+l"(d) : "l"(a), "l"(b));
}

// LayerNorm(+affine)+SiLU over 128-dim columns of h stored [j][e] stride 66.
__device__ __forceinline__ void ln_silu(float* sm, int oh, int og, int obt, int tid) {
  const int e = tid & 63;
  const int q = tid >> 6;          // 0..7, each covers 16 rows
  float s = 0.f, ss = 0.f;
  #pragma unroll
  for (int j = q * 16; j < q * 16 + 16; j++) {
    float v = sm[oh + j * 66 + e];
    s += v; ss += v * v;
  }
  sm[ORED + tid]  = s;
  sm[ORED2 + tid] = ss;
  __syncthreads();
  if (tid < 64) {
    float st = 0.f, sst = 0.f;
    #pragma unroll
    for (int i = 0; i < 8; i++) {
      st  += sm[ORED  + e + 64 * i];
      sst += sm[ORED2 + e + 64 * i];
    }
    float mu  = st * (1.f / 128.f);
    float var = sst * (1.f / 128.f) - mu * mu;
    var = fmaxf(var, 0.f);
    sm[OMU + e] = mu;
    sm[ORS + e] = rsqrtf(var + LN_EPS);
  }
  __syncthreads();
  const float mu = sm[OMU + e];
  const float rs = sm[ORS + e];
  #pragma unroll
  for (int j = q * 16; j < q * 16 + 16; j++) {
    float v = sm[oh + j * 66 + e];
    float y = (v - mu) * rs * sm[og + j] + sm[obt + j];
    float sg = 1.f / (1.f + __expf(-y));
    sm[oh + j * 66 + e] = y * sg;
  }
  __syncthreads();
}

__global__ void __launch_bounds__(NTHREADS, 1)
urmlp_kernel(const float* __restrict__ x,
             const float* __restrict__ W1, const float* __restrict__ b1,
             const float* __restrict__ g1, const float* __restrict__ bt1,
             const float* __restrict__ W2, const float* __restrict__ b2,
             const float* __restrict__ g2, const float* __restrict__ bt2,
             const float* __restrict__ W3, const float* __restrict__ b3,
             float* __restrict__ out, int E) {
  extern __shared__ float sm[];
  const int tid = threadIdx.x;
  const int n   = blockIdx.y;

  // ---- load expert weights to SMEM, transposed to [k][j] ----
  for (int i = tid; i < HID * DIN; i += NTHREADS) {      // W1 slice [128j][64k]
    int j = i >> 6, k = i & 63;
    sm[OWS1 + k * HID + j] = W1[n * HID * DIN + i];
  }
  for (int i = tid; i < HID * HID; i += NTHREADS) {      // W2[n] [128][128]
    int j = i >> 7, k = i & 127;
    sm[OWS2 + k * HID + j] = W2[n * HID * HID + i];
  }
  for (int i = tid; i < DOUT * HID; i += NTHREADS) {     // W3[n] [64][128]
    int j = i >> 7, k = i & 127;
    sm[OWS3 + k * DOUT + j] = W3[n * DOUT * HID + i];
  }
  if (tid < HID) {
    sm[OB1 + tid]  = b1[n * HID + tid];
    sm[OG1 + tid]  = g1[n * HID + tid];
    sm[OBT1 + tid] = bt1[n * HID + tid];
    sm[OB2 + tid]  = b2[n * HID + tid];
    sm[OG2 + tid]  = g2[n * HID + tid];
    sm[OBT2 + tid] = bt2[n * HID + tid];
    if (tid < DOUT) sm[OB3 + tid] = b3[n * DOUT + tid];
  }
  __syncthreads();

  // thread->tile mapping: 16 warps. Within warp: 8 j-groups x 4 e-subgroups.
  const int lane  = tid & 31;
  const int w     = tid >> 5;
  const int egl   = lane >> 3;              // 0..3
  const int jgl   = lane & 7;               // 0..7
  const int jg    = (w >> 2) * 8 + jgl;     // 0..31  -> j = jg*4..+3 (GEMM1/2)
  const int eg    = (w & 3) * 4 + egl;      // 0..15  -> e = eg*4..+3
  const int ebase = eg * 4;

  const int NT = (E + ET - 1) / ET;
  for (int t = blockIdx.x; t < NT; t += gridDim.x) {
    const int e0 = t * ET;

    // ---- load x tile transposed to [k][e], stride 66, zero-fill tail ----
    for (int i = tid; i < ET * DIN; i += NTHREADS) {
      int e = i >> 6, k = i & 63;
      float v = (e0 + e < E) ? x[(size_t)(e0 + e) * DIN + k] : 0.f;
      sm[OXO + k * 66 + e] = v;
    }
    __syncthreads();

    // ---- GEMM1: h1[j][e] = b1[j] + sum_k W1t[k][j] * x[k][e]  (pack over e) ----
    {
      unsigned long long acc[4][2];
      #pragma unroll
      for (int jc = 0; jc < 4; jc++) {
        float b = sm[OB1 + jg * 4 + jc];
        unsigned long long bp = pk2(b, b);
        acc[jc][0] = bp; acc[jc][1] = bp;
      }
      #pragma unroll 4
      for (int k = 0; k < DIN; k++) {
        unsigned long long hp0 = *(const unsigned long long*)&sm[OXO + k * 66 + ebase];
        unsigned long long hp1 = *(const unsigned long long*)&sm[OXO + k * 66 + ebase + 2];
        float4 wv = *(const float4*)&sm[OWS1 + k * HID + jg * 4];
        unsigned long long wp0 = pk2(wv.x, wv.x), wp1 = pk2(wv.y, wv.y);
        unsigned long long wp2 = pk2(wv.z, wv.z), wp3 = pk2(wv.w, wv.w);
        fma2(acc[0][0], hp0, wp0); fma2(acc[0][1], hp1, wp0);
        fma2(acc[1][0], hp0, wp1); fma2(acc[1][1], hp1, wp1);
        fma2(acc[2][0], hp0, wp2); fma2(acc[2][1], hp1, wp2);
        fma2(acc[3][0], hp0, wp3); fma2(acc[3][1], hp1, wp3);
      }
      #pragma unroll
      for (int jc = 0; jc < 4; jc++) {
        int j = jg * 4 + jc;
        *(unsigned long long*)&sm[OH1 + j * 66 + ebase]     = acc[jc][0];
        *(unsigned long long*)&sm[OH1 + j * 66 + ebase + 2] = acc[jc][1];
      }
    }
    __syncthreads();

    ln_silu(sm, OH1, OG1, OBT1, tid);

    // ---- GEMM2: h2[j][e] = b2[j] + sum_k W2t[k][j] * h1[k][e]  (pack over e) ----
    {
      unsigned long long acc[4][2];
      #pragma unroll
      for (int jc = 0; jc < 4; jc++) {
        float b = sm[OB2 + jg * 4 + jc];
        unsigned long long bp = pk2(b, b);
        acc[jc][0] = bp; acc[jc][1] = bp;
      }
      #pragma unroll 2
      for (int k = 0; k < HID; k++) {
        unsigned long long hp0 = *(const unsigned long long*)&sm[OH1 + k * 66 + ebase];
        unsigned long long hp1 = *(const unsigned long long*)&sm[OH1 + k * 66 + ebase + 2];
        float4 wv = *(const float4*)&sm[OWS2 + k * HID + jg * 4];
        unsigned long long wp0 = pk2(wv.x, wv.x), wp1 = pk2(wv.y, wv.y);
        unsigned long long wp2 = pk2(wv.z, wv.z), wp3 = pk2(wv.w, wv.w);
        fma2(acc[0][0], hp0, wp0); fma2(acc[0][1], hp1, wp0);
        fma2(acc[1][0], hp0, wp1); fma2(acc[1][1], hp1, wp1);
        fma2(acc[2][0], hp0, wp2); fma2(acc[2][1], hp1, wp2);
        fma2(acc[3][0], hp0, wp3); fma2(acc[3][1], hp1, wp3);
      }
      #pragma unroll
      for (int jc = 0; jc < 4; jc++) {
        int j = jg * 4 + jc;
        *(unsigned long long*)&sm[OH2 + j * 66 + ebase]     = acc[jc][0];
        *(unsigned long long*)&sm[OH2 + j * 66 + ebase + 2] = acc[jc][1];
      }
    }
    __syncthreads();

    ln_silu(sm, OH2, OG2, OBT2, tid);

    // ---- GEMM3: o[e][j] = b3[j] + sum_k W3t[k][j] * h2[k][e]  (pack over e) ----
    {
      unsigned long long acc[2][2];
      #pragma unroll
      for (int jc = 0; jc < 2; jc++) {
        float b = sm[OB3 + jg * 2 + jc];
        unsigned long long bp = pk2(b, b);
        acc[jc][0] = bp; acc[jc][1] = bp;
      }
      #pragma unroll 2
      for (int k = 0; k < HID; k++) {
        unsigned long long hp0 = *(const unsigned long long*)&sm[OH2 + k * 66 + ebase];
        unsigned long long hp1 = *(const unsigned long long*)&sm[OH2 + k * 66 + ebase + 2];
        float2 wv = *(const float2*)&sm[OWS3 + k * DOUT + jg * 2];
        unsigned long long wp0 = pk2(wv.x, wv.x), wp1 = pk2(wv.y, wv.y);
        fma2(acc[0][0], hp0, wp0); fma2(acc[0][1], hp1, wp0);
        fma2(acc[1][0], hp0, wp1); fma2(acc[1][1], hp1, wp1);
      }
      // stage output as [e][j], stride 68
      #pragma unroll
      for (int jc = 0; jc < 2; jc++) {
        int j = jg * 2 + jc;
        #pragma unroll
        for (int p = 0; p < 2; p++) {
          float lo, hi;
          upk2(acc[jc][p], lo, hi);
          sm[OXO + (ebase + 2 * p + 0) * 68 + j] = lo;
          sm[OXO + (ebase + 2 * p + 1) * 68 + j] = hi;
        }
      }
    }
    __syncthreads();

    // ---- coalesced global store: out[n][e][j] ----
    {
      const size_t obase = (size_t)n * E * DOUT + (size_t)e0 * DOUT;
      #pragma unroll
      for (int r = 0; r < 2; r++) {
        int v = tid + r * NTHREADS;     // 0..1023 float4 slots
        int e = v >> 4, jq = v & 15;
        if (e0 + e < E) {
          float4 val = *(const float4*)&sm[OXO + e * 68 + jq * 4];
          *(float4*)&out[obase + (size_t)e * DOUT + jq * 4] = val;
        }
      }
    }
    __syncthreads();   // protect OXO before next tile's x load
  }
}

extern "C" void kernel_launch(void* const* d_in, const int* in_sizes, int n_in,
                              void* d_out, int out_size) {
  const float* x   = (const float*)d_in[0];
  const float* W1  = (const float*)d_in[1];
  const float* b1  = (const float*)d_in[2];
  const float* g1  = (const float*)d_in[3];
  const float* bt1 = (const float*)d_in[4];
  const float* W2  = (const float*)d_in[5];
  const float* b2  = (const float*)d_in[6];
  const float* g2  = (const float*)d_in[7];
  const float* bt2 = (const float*)d_in[8];
  const float* W3  = (const float*)d_in[9];
  const float* b3  = (const float*)d_in[10];
  float* out = (float*)d_out;
  const int E = in_sizes[0] / DIN;

  cudaFuncSetAttribute(urmlp_kernel, cudaFuncAttributeMaxDynamicSharedMemorySize,
                       SMEMF * sizeof(float));
  dim3 grid(GRIDX, NEXP);
  urmlp_kernel<<<grid, NTHREADS, SMEMF * sizeof(float)>>>(
      x, W1, b1, g1, bt1, W2, b2, g2, bt2, W3, b3, out, E);
}